// round 9
// baseline (speedup 1.0000x reference)
#include <cuda_runtime.h>
#include <math.h>
#include <stdint.h>

#define B_   4096
#define J_   32
#define E_   256
#define ROWS (B_ * J_)

// ======================= scratch (device globals) ==========================
__device__ float g_c1[B_ * E_];     // bias + x @ W^T
__device__ float g_c2[J_ * E_];     // keys @ V^T
__device__ float g_xk[B_ * J_];     // x . key_j   (raw dot, pre-sigmoid)

// ======================= PTX helpers =======================================
__device__ __forceinline__ uint32_t smem_u32(const void* p) {
    uint32_t a;
    asm("{ .reg .u64 t; cvta.to.shared.u64 t, %1; cvt.u32.u64 %0, t; }"
        : "=r"(a) : "l"(p));
    return a;
}

#define CP_ASYNC16(dst, src)                                                  \
    asm volatile("cp.async.cg.shared.global [%0], [%1], 16;"                  \
        :: "r"(dst), "l"(__cvta_generic_to_global((const void*)(src))) : "memory")

#define MBAR_INIT(addr, cnt)                                                  \
    asm volatile("mbarrier.init.shared.b64 [%0], %1;" :: "r"(addr), "r"(cnt) : "memory")

// arrive when ALL prior cp.async of this thread have completed (no count inc)
#define CP_MBAR_ARRIVE(addr)                                                  \
    asm volatile("cp.async.mbarrier.arrive.noinc.shared.b64 [%0];"            \
        :: "r"(addr) : "memory")

#define MBAR_ARRIVE(addr)                                                     \
    asm volatile("mbarrier.arrive.shared.b64 _, [%0];" :: "r"(addr) : "memory")

#define MBAR_WAIT(addr, parity) do {                                          \
    asm volatile("{\n\t.reg .pred P;\n\t"                                     \
        "WL_%=:\n\t"                                                          \
        "mbarrier.try_wait.parity.shared.b64 P, [%0], %1;\n\t"                \
        "@P bra.uni WD_%=;\n\t"                                               \
        "bra.uni WL_%=;\n\t"                                                  \
        "WD_%=:\n\t}"                                                         \
        :: "r"(addr), "r"(parity) : "memory");                                \
} while (0)

__device__ __forceinline__ void mma_tf32(float* d, const uint32_t* a,
                                         const uint32_t* b) {
    asm volatile(
        "mma.sync.aligned.m16n8k8.row.col.f32.tf32.tf32.f32 "
        "{%0,%1,%2,%3}, {%4,%5,%6,%7}, {%8,%9}, {%0,%1,%2,%3};"
        : "+f"(d[0]), "+f"(d[1]), "+f"(d[2]), "+f"(d[3])
        : "r"(a[0]), "r"(a[1]), "r"(a[2]), "r"(a[3]), "r"(b[0]), "r"(b[1]));
}

__device__ __forceinline__ void ldsm_x4(uint32_t* r, uint32_t addr) {
    asm volatile("ldmatrix.sync.aligned.m8n8.x4.shared.b16 {%0,%1,%2,%3}, [%4];"
        : "=r"(r[0]), "=r"(r[1]), "=r"(r[2]), "=r"(r[3]) : "r"(addr));
}
__device__ __forceinline__ void ldsm_x2(uint32_t* r, uint32_t addr) {
    asm volatile("ldmatrix.sync.aligned.m8n8.x2.shared.b16 {%0,%1}, [%2];"
        : "=r"(r[0]), "=r"(r[1]) : "r"(addr));
}

// ======================= shared GEMM config ================================
// 512 thr (16 warps, 4m x 4n), warp tile 32x64. CTA tile M=128, N=256,
// K=256 in 16 chunks of 16. A resident (pitch 260, raw fp32 -> HW tf32).
// B: 4-stage mbarrier ring via cp.async (pitch 20) -- NO __syncthreads in
// the K loop; warps free-run with up to 3 chunks of skew.
#define PA    260
#define PB    20
#define NCH   16                     // K chunks
#define AF    33280                  // 128*260 floats; B stages follow
#define BSTG  5120                   // 256*20 floats per stage
#define XF    (AF + 4 * BSTG)        // 53760 : x tile (4x256) / bias
#define GF    (XF + 1024)            // 54784 : gate[128]
#define REDF  (GF + 128)             // 54912 : red[128*4]
#define INVF  (REDF + 512)           // 55424 : inv[128]
#define MBARF (INVF + 128)           // 55552 : 8 mbarriers (64 B)
#define SMEMF (MBARF + 16)           // 55568 floats
#define MAIN_SMEM (SMEMF * 4)        // 222272 bytes -> 1 CTA/SM

// Stage the 128x256 A tile via cp.async (512 threads).
__device__ __forceinline__ void stage_a(const float* __restrict__ Ag,
                                        int row0, uint32_t sb, int tid)
{
    #pragma unroll
    for (int i = 0; i < 16; ++i) {
        int idx = tid + (i << 9);
        int r = idx >> 6, c4 = idx & 63;
        CP_ASYNC16(sb + (uint32_t)(r * PA + c4 * 4) * 4u,
                   Ag + (size_t)(row0 + r) * E_ + c4 * 4);
    }
}

// Issue the 2 cp.asyncs of B chunk p (all 512 threads) + noinc arrive.
__device__ __forceinline__ void produce_chunk(const float* __restrict__ Bg,
                                              uint32_t sb, uint32_t mb,
                                              int tid, int p)
{
    uint32_t bst = sb + (uint32_t)(AF + (p & 3) * BSTG) * 4u;
    #pragma unroll
    for (int i = 0; i < 2; ++i) {
        int idx = tid + (i << 9);
        int f = idx >> 2, k4 = idx & 3;
        CP_ASYNC16(bst + (uint32_t)(f * PB + k4 * 4) * 4u,
                   Bg + (size_t)f * E_ + p * 16 + k4 * 4);
    }
    CP_MBAR_ARRIVE(mb + (uint32_t)(p & 3) * 8u);   // full[p&3]
}

// Mainloop: acc += A_tile @ Bg^T  (Bg is 256x256 row-major [n][k]).
// Caller must have: init'd mbarriers + __syncthreads, then issued the A
// (and extra) cp.asyncs -- chunk 0's arrive tracks them too.
__device__ __forceinline__ void tf32_mainloop(const float* __restrict__ Bg,
    uint32_t sb, int tid, float acc[2][8][4])
{
    const int lane = tid & 31;
    const int wid  = tid >> 5;
    const int mwarp = wid >> 2;       // 0..3 (32 rows)
    const int nwarp = wid & 3;        // 0..3 (64 cols)
    const uint32_t mb  = sb + (uint32_t)MBARF * 4u;  // full[0..3]
    const uint32_t mbe = mb + 32u;                   // empty[0..3]

    const uint32_t a_base = sb
        + (uint32_t)((mwarp * 32 + (lane & 15)) * PA + ((lane >> 4) << 2)) * 4u;
    const uint32_t b_lane =
        (uint32_t)((nwarp * 64 + (lane & 7)) * PB + (((lane >> 3) & 1) << 2)) * 4u;

    produce_chunk(Bg, sb, mb, tid, 0);
    produce_chunk(Bg, sb, mb, tid, 1);
    produce_chunk(Bg, sb, mb, tid, 2);

    #pragma unroll 1
    for (int c = 0; c < NCH; ++c) {
        int cp = c + 3;
        if (cp < NCH) {
            int q2 = cp >> 2;
            if (q2 >= 1)
                MBAR_WAIT(mbe + (uint32_t)(cp & 3) * 8u, (q2 - 1) & 1);
            produce_chunk(Bg, sb, mb, tid, cp);
        }
        MBAR_WAIT(mb + (uint32_t)(c & 3) * 8u, (c >> 2) & 1);

        const uint32_t a_c = a_base + (uint32_t)c * 64u;    // A: global k
        const uint32_t b_c = sb + (uint32_t)(AF + (c & 3) * BSTG) * 4u + b_lane;
        #pragma unroll
        for (int ks = 0; ks < 2; ++ks) {
            uint32_t afr[2][4];
            ldsm_x4(afr[0], a_c + ks * 32u);
            ldsm_x4(afr[1], a_c + 16u * PA * 4u + ks * 32u);
            uint32_t bfr[8][2];
            #pragma unroll
            for (int nt = 0; nt < 8; ++nt)
                ldsm_x2(bfr[nt], b_c + (uint32_t)nt * (8u * PB * 4u) + ks * 32u);
            #pragma unroll
            for (int nt = 0; nt < 8; ++nt) {
                mma_tf32(acc[0][nt], afr[0], bfr[nt]);
                mma_tf32(acc[1][nt], afr[1], bfr[nt]);
            }
        }
        MBAR_ARRIVE(mbe + (uint32_t)(c & 3) * 8u);
    }
}

__device__ __forceinline__ void init_ring(uint32_t sb, int tid)
{
    if (tid == 0) {
        uint32_t mb = sb + (uint32_t)MBARF * 4u;
        #pragma unroll
        for (int s = 0; s < 4; ++s) {
            MBAR_INIT(mb + s * 8u, 512);        // full
            MBAR_INIT(mb + 32u + s * 8u, 512);  // empty
        }
    }
    __syncthreads();
}

// ======================= main fused kernel =================================
__global__ void __launch_bounds__(512, 1)
memcell_mma(const float* __restrict__ state, const float* __restrict__ U,
            const float* __restrict__ x, float* __restrict__ out)
{
    extern __shared__ float sm[];
    const int tid  = threadIdx.x;
    const int lane = tid & 31;
    const int wid  = tid >> 5;
    const int grp  = lane >> 2;
    const int tig  = lane & 3;
    const int mwarp = wid >> 2;
    const int nwarp = wid & 3;
    const int row0 = blockIdx.x * 128;
    const uint32_t sb = smem_u32(sm);

    init_ring(sb, tid);

    // stage A (state) + x tile (4 rows x 256); tracked by chunk-0 arrive
    stage_a(state, row0, sb, tid);
    if (tid < 256)
        CP_ASYNC16(sb + (uint32_t)(XF + tid * 4) * 4u,
                   x + (size_t)(row0 >> 5) * E_ + tid * 4);

    float acc[2][8][4];
    #pragma unroll
    for (int mt = 0; mt < 2; ++mt)
        #pragma unroll
        for (int nt = 0; nt < 8; ++nt)
            #pragma unroll
            for (int q = 0; q < 4; ++q) acc[mt][nt][q] = 0.f;

    tf32_mainloop(U, sb, tid, acc);

    // ---- fused gate from resident A tile: 4 threads per row ----
    {
        int r = tid >> 2, q = tid & 3;
        const float* arow = sm + r * PA;
        const float* xrow = sm + XF + (r >> 5) * 256;
        float dot = 0.f;
        #pragma unroll
        for (int u = 0; u < 16; ++u) {
            int f4 = u * 4 + q;
            float4 av = *reinterpret_cast<const float4*>(arow + f4 * 4);
            float4 xv = *reinterpret_cast<const float4*>(xrow + f4 * 4);
            dot += av.x * xv.x + av.y * xv.y + av.z * xv.z + av.w * xv.w;
        }
        dot += __shfl_xor_sync(0xffffffffu, dot, 1);
        dot += __shfl_xor_sync(0xffffffffu, dot, 2);
        if (q == 0)
            sm[GF + r] = 1.f / (1.f + expf(-(dot + g_xk[row0 + r])));
    }
    __syncthreads();

    // ---- epilogue pass 1: v = s + g*relu(acc + c1 + c2) -> A smem ----
    float* red = sm + REDF;
    float* inv = sm + INVF;
    #pragma unroll
    for (int mt = 0; mt < 2; ++mt) {
        #pragma unroll
        for (int r2 = 0; r2 < 2; ++r2) {
            int rl   = mwarp * 32 + mt * 16 + grp + r2 * 8;
            int grow = row0 + rl;
            float gv = sm[GF + rl];
            const float* c1r = g_c1 + (size_t)(grow >> 5) * E_;
            const float* c2r = g_c2 + (size_t)(grow & 31) * E_;
            float ss = 0.f;
            #pragma unroll
            for (int nt = 0; nt < 8; ++nt) {
                int col = nwarp * 64 + nt * 8 + tig * 2;
                float2 sv  = *reinterpret_cast<float2*>(sm + rl * PA + col);
                float2 c1v = *reinterpret_cast<const float2*>(c1r + col);
                float2 c2v = *reinterpret_cast<const float2*>(c2r + col);
                float d0 = acc[mt][nt][r2 * 2 + 0] + c1v.x + c2v.x;
                float d1 = acc[mt][nt][r2 * 2 + 1] + c1v.y + c2v.y;
                float v0 = sv.x + gv * fmaxf(d0, 0.f);
                float v1 = sv.y + gv * fmaxf(d1, 0.f);
                ss += v0 * v0 + v1 * v1;
                *reinterpret_cast<float2*>(sm + rl * PA + col) = make_float2(v0, v1);
            }
            ss += __shfl_xor_sync(0xffffffffu, ss, 1);
            ss += __shfl_xor_sync(0xffffffffu, ss, 2);
            if (tig == 0) red[rl * 4 + nwarp] = ss;
        }
    }
    __syncthreads();
    if (tid < 128) {
        float s = red[tid * 4] + red[tid * 4 + 1]
                + red[tid * 4 + 2] + red[tid * 4 + 3];
        inv[tid] = 1.f / (sqrtf(s) + 1e-8f);
    }
    __syncthreads();

    // ---- epilogue pass 2: coalesced normalized writeback ----
    #pragma unroll
    for (int i = 0; i < 16; ++i) {
        int idx = tid + (i << 9);
        int r = idx >> 6, c4 = idx & 63;
        float iv = inv[r];
        float4 v = *reinterpret_cast<float4*>(sm + r * PA + c4 * 4);
        v.x *= iv; v.y *= iv; v.z *= iv; v.w *= iv;
        reinterpret_cast<float4*>(out + (size_t)(row0 + r) * E_)[c4] = v;
    }
}

// ======================= c1 via the same MMA mainloop ======================
// g_c1[row][f] = bias[f] + sum_e x[row][e] * W[f][e]
__global__ void __launch_bounds__(512, 1)
c1_mma(const float* __restrict__ x, const float* __restrict__ W,
       const float* __restrict__ bias)
{
    extern __shared__ float sm[];
    const int tid  = threadIdx.x;
    const int lane = tid & 31;
    const int wid  = tid >> 5;
    const int grp  = lane >> 2;
    const int tig  = lane & 3;
    const int mwarp = wid >> 2;
    const int nwarp = wid & 3;
    const int row0 = blockIdx.x * 128;
    const uint32_t sb = smem_u32(sm);

    init_ring(sb, tid);

    stage_a(x, row0, sb, tid);
    if (tid < 64)   // bias -> smem (256 floats)
        CP_ASYNC16(sb + (uint32_t)(XF + tid * 4) * 4u, bias + tid * 4);

    float acc[2][8][4];
    #pragma unroll
    for (int mt = 0; mt < 2; ++mt)
        #pragma unroll
        for (int nt = 0; nt < 8; ++nt)
            #pragma unroll
            for (int q = 0; q < 4; ++q) acc[mt][nt][q] = 0.f;

    tf32_mainloop(W, sb, tid, acc);

    #pragma unroll
    for (int mt = 0; mt < 2; ++mt) {
        #pragma unroll
        for (int r2 = 0; r2 < 2; ++r2) {
            int rl  = mwarp * 32 + mt * 16 + grp + r2 * 8;
            int row = row0 + rl;
            #pragma unroll
            for (int nt = 0; nt < 8; ++nt) {
                int col = nwarp * 64 + nt * 8 + tig * 2;
                float2 bv = *reinterpret_cast<const float2*>(sm + XF + col);
                float2 o  = make_float2(acc[mt][nt][r2 * 2 + 0] + bv.x,
                                        acc[mt][nt][r2 * 2 + 1] + bv.y);
                *reinterpret_cast<float2*>(g_c1 + (size_t)row * E_ + col) = o;
            }
        }
    }
}

// ======================= tiny side kernels =================================
__global__ void gemm_c2(const float* __restrict__ keys, const float* __restrict__ V)
{
    __shared__ float ks[E_];
    int j = blockIdx.x;
    int f = threadIdx.x;
    ks[f] = keys[j * E_ + f];
    __syncthreads();
    const float4* vp = reinterpret_cast<const float4*>(V) + (size_t)f * (E_ / 4);
    const float4* kp = reinterpret_cast<const float4*>(ks);
    float a = 0.f;
    #pragma unroll
    for (int e4 = 0; e4 < E_ / 4; ++e4) {
        float4 vv = vp[e4], k = kp[e4];
        a += vv.x * k.x + vv.y * k.y + vv.z * k.z + vv.w * k.w;
    }
    g_c2[j * E_ + f] = a;
}

// xk[b][j] = dot(x_b, key_j)
__global__ void __launch_bounds__(256) xk_kernel(const float* __restrict__ x,
                                                 const float* __restrict__ keys)
{
    __shared__ float4 xs[E_ / 4];
    int b = blockIdx.x, tid = threadIdx.x;
    if (tid < E_ / 4) xs[tid] = reinterpret_cast<const float4*>(x + (size_t)b * E_)[tid];
    __syncthreads();

    int warp = tid >> 5, lane = tid & 31;
    #pragma unroll
    for (int t = 0; t < 4; ++t) {
        int jj = warp + t * 8;
        const float4* kp = reinterpret_cast<const float4*>(keys + (size_t)jj * E_);
        float p = 0.f;
        #pragma unroll
        for (int q = 0; q < 2; ++q) {
            float4 k = kp[lane + 32 * q];
            float4 xv = xs[lane + 32 * q];
            p += xv.x * k.x + xv.y * k.y + xv.z * k.z + xv.w * k.w;
        }
        #pragma unroll
        for (int o = 16; o; o >>= 1) p += __shfl_xor_sync(0xffffffffu, p, o);
        if (lane == 0) g_xk[b * J_ + jj] = p;
    }
}

// ===========================================================================
extern "C" void kernel_launch(void* const* d_in, const int* in_sizes, int n_in,
                              void* d_out, int out_size)
{
    const float* x     = (const float*)d_in[0];
    const float* state = (const float*)d_in[1];
    const float* keys  = (const float*)d_in[2];
    const float* U     = (const float*)d_in[3];
    const float* V     = (const float*)d_in[4];
    const float* W     = (const float*)d_in[5];
    const float* bias  = (const float*)d_in[6];
    float* out = (float*)d_out;

    cudaFuncSetAttribute(c1_mma,      cudaFuncAttributeMaxDynamicSharedMemorySize, MAIN_SMEM);
    cudaFuncSetAttribute(memcell_mma, cudaFuncAttributeMaxDynamicSharedMemorySize, MAIN_SMEM);

    gemm_c2<<<J_, E_>>>(keys, V);
    xk_kernel<<<B_, 256>>>(x, keys);
    c1_mma<<<B_ / 128, 512, MAIN_SMEM>>>(x, W, bias);
    memcell_mma<<<ROWS / 128, 512, MAIN_SMEM>>>(state, U, x, out);
}

// round 10
// speedup vs baseline: 1.0476x; 1.0476x over previous
#include <cuda_runtime.h>
#include <math.h>
#include <stdint.h>

#define B_   4096
#define J_   32
#define E_   256
#define ROWS (B_ * J_)

// ======================= scratch (device globals) ==========================
__device__ float g_c1[B_ * E_];     // bias + x @ W^T
__device__ float g_c2[J_ * E_];     // keys @ V^T
__device__ float g_xk[B_ * J_];     // x . key_j   (raw dot, pre-sigmoid)

// ======================= PTX helpers =======================================
__device__ __forceinline__ uint32_t smem_u32(const void* p) {
    uint32_t a;
    asm("{ .reg .u64 t; cvta.to.shared.u64 t, %1; cvt.u32.u64 %0, t; }"
        : "=r"(a) : "l"(p));
    return a;
}

#define CP_ASYNC16(dst, src)                                                  \
    asm volatile("cp.async.cg.shared.global [%0], [%1], 16;"                  \
        :: "r"(dst), "l"(__cvta_generic_to_global((const void*)(src))) : "memory")

#define MBAR_INIT(addr, cnt)                                                  \
    asm volatile("mbarrier.init.shared.b64 [%0], %1;" :: "r"(addr), "r"(cnt) : "memory")

#define CP_MBAR_ARRIVE(addr)                                                  \
    asm volatile("cp.async.mbarrier.arrive.noinc.shared.b64 [%0];"            \
        :: "r"(addr) : "memory")

#define MBAR_ARRIVE(addr)                                                     \
    asm volatile("mbarrier.arrive.shared.b64 _, [%0];" :: "r"(addr) : "memory")

#define MBAR_WAIT(addr, parity) do {                                          \
    asm volatile("{\n\t.reg .pred P;\n\t"                                     \
        "WL_%=:\n\t"                                                          \
        "mbarrier.try_wait.parity.shared.b64 P, [%0], %1;\n\t"                \
        "@P bra.uni WD_%=;\n\t"                                               \
        "bra.uni WL_%=;\n\t"                                                  \
        "WD_%=:\n\t}"                                                         \
        :: "r"(addr), "r"(parity) : "memory");                                \
} while (0)

__device__ __forceinline__ void mma_tf32(float* d, const uint32_t* a,
                                         const uint32_t* b) {
    asm volatile(
        "mma.sync.aligned.m16n8k8.row.col.f32.tf32.tf32.f32 "
        "{%0,%1,%2,%3}, {%4,%5,%6,%7}, {%8,%9}, {%0,%1,%2,%3};"
        : "+f"(d[0]), "+f"(d[1]), "+f"(d[2]), "+f"(d[3])
        : "r"(a[0]), "r"(a[1]), "r"(a[2]), "r"(a[3]), "r"(b[0]), "r"(b[1]));
}

__device__ __forceinline__ void ldsm_x4(uint32_t* r, uint32_t addr) {
    asm volatile("ldmatrix.sync.aligned.m8n8.x4.shared.b16 {%0,%1,%2,%3}, [%4];"
        : "=r"(r[0]), "=r"(r[1]), "=r"(r[2]), "=r"(r[3]) : "r"(addr));
}
__device__ __forceinline__ void ldsm_x2(uint32_t* r, uint32_t addr) {
    asm volatile("ldmatrix.sync.aligned.m8n8.x2.shared.b16 {%0,%1}, [%2];"
        : "=r"(r[0]), "=r"(r[1]) : "r"(addr));
}

// ======================= main kernel config (R9, proven) ===================
#define PA    260
#define PB    20
#define NCH   16                     // K chunks
#define AF    33280                  // 128*260 floats; B stages follow
#define BSTG  5120                   // 256*20 floats per stage
#define XF    (AF + 4 * BSTG)        // 53760 : x tile (4x256)
#define GF    (XF + 1024)            // 54784 : gate[128]
#define REDF  (GF + 128)             // 54912 : red[128*4]
#define INVF  (REDF + 512)           // 55424 : inv[128]
#define MBARF (INVF + 128)           // 55552 : 8 mbarriers (64 B)
#define SMEMF (MBARF + 16)           // 55568 floats
#define MAIN_SMEM (SMEMF * 4)        // 222272 bytes -> 1 CTA/SM

// Stage the 128x256 A tile via cp.async (512 threads).
__device__ __forceinline__ void stage_a(const float* __restrict__ Ag,
                                        int row0, uint32_t sb, int tid)
{
    #pragma unroll
    for (int i = 0; i < 16; ++i) {
        int idx = tid + (i << 9);
        int r = idx >> 6, c4 = idx & 63;
        CP_ASYNC16(sb + (uint32_t)(r * PA + c4 * 4) * 4u,
                   Ag + (size_t)(row0 + r) * E_ + c4 * 4);
    }
}

// Issue the cp.asyncs of B chunk p (512 threads) + noinc arrive.
__device__ __forceinline__ void produce_chunk(const float* __restrict__ Bg,
                                              uint32_t sb, uint32_t mb,
                                              int tid, int p)
{
    uint32_t bst = sb + (uint32_t)(AF + (p & 3) * BSTG) * 4u;
    #pragma unroll
    for (int i = 0; i < 2; ++i) {
        int idx = tid + (i << 9);
        int f = idx >> 2, k4 = idx & 3;
        CP_ASYNC16(bst + (uint32_t)(f * PB + k4 * 4) * 4u,
                   Bg + (size_t)f * E_ + p * 16 + k4 * 4);
    }
    CP_MBAR_ARRIVE(mb + (uint32_t)(p & 3) * 8u);   // full[p&3]
}

__device__ __forceinline__ void tf32_mainloop(const float* __restrict__ Bg,
    uint32_t sb, int tid, float acc[2][8][4])
{
    const int lane = tid & 31;
    const int wid  = tid >> 5;
    const int mwarp = wid >> 2;       // 0..3 (32 rows)
    const int nwarp = wid & 3;        // 0..3 (64 cols)
    const uint32_t mb  = sb + (uint32_t)MBARF * 4u;  // full[0..3]
    const uint32_t mbe = mb + 32u;                   // empty[0..3]

    const uint32_t a_base = sb
        + (uint32_t)((mwarp * 32 + (lane & 15)) * PA + ((lane >> 4) << 2)) * 4u;
    const uint32_t b_lane =
        (uint32_t)((nwarp * 64 + (lane & 7)) * PB + (((lane >> 3) & 1) << 2)) * 4u;

    produce_chunk(Bg, sb, mb, tid, 0);
    produce_chunk(Bg, sb, mb, tid, 1);
    produce_chunk(Bg, sb, mb, tid, 2);

    #pragma unroll 1
    for (int c = 0; c < NCH; ++c) {
        int cp = c + 3;
        if (cp < NCH) {
            int q2 = cp >> 2;
            if (q2 >= 1)
                MBAR_WAIT(mbe + (uint32_t)(cp & 3) * 8u, (q2 - 1) & 1);
            produce_chunk(Bg, sb, mb, tid, cp);
        }
        MBAR_WAIT(mb + (uint32_t)(c & 3) * 8u, (c >> 2) & 1);

        const uint32_t a_c = a_base + (uint32_t)c * 64u;    // A: global k
        const uint32_t b_c = sb + (uint32_t)(AF + (c & 3) * BSTG) * 4u + b_lane;
        #pragma unroll
        for (int ks = 0; ks < 2; ++ks) {
            uint32_t afr[2][4];
            ldsm_x4(afr[0], a_c + ks * 32u);
            ldsm_x4(afr[1], a_c + 16u * PA * 4u + ks * 32u);
            uint32_t bfr[8][2];
            #pragma unroll
            for (int nt = 0; nt < 8; ++nt)
                ldsm_x2(bfr[nt], b_c + (uint32_t)nt * (8u * PB * 4u) + ks * 32u);
            #pragma unroll
            for (int nt = 0; nt < 8; ++nt) {
                mma_tf32(acc[0][nt], afr[0], bfr[nt]);
                mma_tf32(acc[1][nt], afr[1], bfr[nt]);
            }
        }
        MBAR_ARRIVE(mbe + (uint32_t)(c & 3) * 8u);
    }
}

__device__ __forceinline__ void init_ring(uint32_t mb, int tid, int cnt)
{
    if (tid == 0) {
        #pragma unroll
        for (int s = 0; s < 4; ++s) {
            MBAR_INIT(mb + s * 8u, cnt);        // full
            MBAR_INIT(mb + 32u + s * 8u, cnt);  // empty
        }
    }
    __syncthreads();
}

// ======================= main fused kernel (R9 verbatim) ===================
__global__ void __launch_bounds__(512, 1)
memcell_mma(const float* __restrict__ state, const float* __restrict__ U,
            const float* __restrict__ x, float* __restrict__ out)
{
    extern __shared__ float sm[];
    const int tid  = threadIdx.x;
    const int lane = tid & 31;
    const int wid  = tid >> 5;
    const int grp  = lane >> 2;
    const int tig  = lane & 3;
    const int mwarp = wid >> 2;
    const int nwarp = wid & 3;
    const int row0 = blockIdx.x * 128;
    const uint32_t sb = smem_u32(sm);

    init_ring(sb + (uint32_t)MBARF * 4u, tid, 512);

    // stage A (state) + x tile (4 rows x 256); tracked by chunk-0 arrive
    stage_a(state, row0, sb, tid);
    if (tid < 256)
        CP_ASYNC16(sb + (uint32_t)(XF + tid * 4) * 4u,
                   x + (size_t)(row0 >> 5) * E_ + tid * 4);

    float acc[2][8][4];
    #pragma unroll
    for (int mt = 0; mt < 2; ++mt)
        #pragma unroll
        for (int nt = 0; nt < 8; ++nt)
            #pragma unroll
            for (int q = 0; q < 4; ++q) acc[mt][nt][q] = 0.f;

    tf32_mainloop(U, sb, tid, acc);

    // ---- fused gate from resident A tile: 4 threads per row ----
    {
        int r = tid >> 2, q = tid & 3;
        const float* arow = sm + r * PA;
        const float* xrow = sm + XF + (r >> 5) * 256;
        float dot = 0.f;
        #pragma unroll
        for (int u = 0; u < 16; ++u) {
            int f4 = u * 4 + q;
            float4 av = *reinterpret_cast<const float4*>(arow + f4 * 4);
            float4 xv = *reinterpret_cast<const float4*>(xrow + f4 * 4);
            dot += av.x * xv.x + av.y * xv.y + av.z * xv.z + av.w * xv.w;
        }
        dot += __shfl_xor_sync(0xffffffffu, dot, 1);
        dot += __shfl_xor_sync(0xffffffffu, dot, 2);
        if (q == 0)
            sm[GF + r] = 1.f / (1.f + expf(-(dot + g_xk[row0 + r])));
    }
    __syncthreads();

    // ---- epilogue pass 1: v = s + g*relu(acc + c1 + c2) -> A smem ----
    float* red = sm + REDF;
    float* inv = sm + INVF;
    #pragma unroll
    for (int mt = 0; mt < 2; ++mt) {
        #pragma unroll
        for (int r2 = 0; r2 < 2; ++r2) {
            int rl   = mwarp * 32 + mt * 16 + grp + r2 * 8;
            int grow = row0 + rl;
            float gv = sm[GF + rl];
            const float* c1r = g_c1 + (size_t)(grow >> 5) * E_;
            const float* c2r = g_c2 + (size_t)(grow & 31) * E_;
            float ss = 0.f;
            #pragma unroll
            for (int nt = 0; nt < 8; ++nt) {
                int col = nwarp * 64 + nt * 8 + tig * 2;
                float2 sv  = *reinterpret_cast<float2*>(sm + rl * PA + col);
                float2 c1v = *reinterpret_cast<const float2*>(c1r + col);
                float2 c2v = *reinterpret_cast<const float2*>(c2r + col);
                float d0 = acc[mt][nt][r2 * 2 + 0] + c1v.x + c2v.x;
                float d1 = acc[mt][nt][r2 * 2 + 1] + c1v.y + c2v.y;
                float v0 = sv.x + gv * fmaxf(d0, 0.f);
                float v1 = sv.y + gv * fmaxf(d1, 0.f);
                ss += v0 * v0 + v1 * v1;
                *reinterpret_cast<float2*>(sm + rl * PA + col) = make_float2(v0, v1);
            }
            ss += __shfl_xor_sync(0xffffffffu, ss, 1);
            ss += __shfl_xor_sync(0xffffffffu, ss, 2);
            if (tig == 0) red[rl * 4 + nwarp] = ss;
        }
    }
    __syncthreads();
    if (tid < 128) {
        float s = red[tid * 4] + red[tid * 4 + 1]
                + red[tid * 4 + 2] + red[tid * 4 + 3];
        inv[tid] = 1.f / (sqrtf(s) + 1e-8f);
    }
    __syncthreads();

    // ---- epilogue pass 2: coalesced normalized writeback ----
    #pragma unroll
    for (int i = 0; i < 16; ++i) {
        int idx = tid + (i << 9);
        int r = idx >> 6, c4 = idx & 63;
        float iv = inv[r];
        float4 v = *reinterpret_cast<float4*>(sm + r * PA + c4 * 4);
        v.x *= iv; v.y *= iv; v.z *= iv; v.w *= iv;
        reinterpret_cast<float4*>(out + (size_t)(row0 + r) * E_)[c4] = v;
    }
}

// ======================= c1: M=32 tiles, 128 CTAs ==========================
// g_c1[row][f] = bias[f] + sum_e x[row][e] * W[f][e]
// 256 thr (8 warps, 2m x 4n), warp tile 16x64. Same 4-stage B ring.
#define AF1    8320                  // 32*260 floats; B stages follow
#define XF1    (AF1 + 4 * BSTG)      // 28800 : bias (256 floats)
#define MB1F   (XF1 + 256)           // 29056 : 8 mbarriers
#define SMEM1F (MB1F + 16)           // 29072 floats
#define C1_SMEM (SMEM1F * 4)         // 116288 bytes

__device__ __forceinline__ void produce_chunk_c1(const float* __restrict__ Bg,
                                                 uint32_t sb, uint32_t mb,
                                                 int tid, int p)
{
    uint32_t bst = sb + (uint32_t)(AF1 + (p & 3) * BSTG) * 4u;
    #pragma unroll
    for (int i = 0; i < 4; ++i) {
        int idx = tid + (i << 8);
        int f = idx >> 2, k4 = idx & 3;
        CP_ASYNC16(bst + (uint32_t)(f * PB + k4 * 4) * 4u,
                   Bg + (size_t)f * E_ + p * 16 + k4 * 4);
    }
    CP_MBAR_ARRIVE(mb + (uint32_t)(p & 3) * 8u);
}

__global__ void __launch_bounds__(256, 1)
c1_mma(const float* __restrict__ x, const float* __restrict__ W,
       const float* __restrict__ bias)
{
    extern __shared__ float sm[];
    const int tid  = threadIdx.x;
    const int lane = tid & 31;
    const int wid  = tid >> 5;
    const int grp  = lane >> 2;
    const int tig  = lane & 3;
    const int mwarp = wid >> 2;       // 0..1 (16 rows each)
    const int nwarp = wid & 3;        // 0..3 (64 cols)
    const int row0 = blockIdx.x * 32;
    const uint32_t sb = smem_u32(sm);
    const uint32_t mb  = sb + (uint32_t)MB1F * 4u;
    const uint32_t mbe = mb + 32u;

    init_ring(mb, tid, 256);

    // stage A = x rows [row0, row0+32) ; bias. Tracked by chunk-0 arrive.
    #pragma unroll
    for (int i = 0; i < 8; ++i) {
        int idx = tid + (i << 8);
        int r = idx >> 6, c4 = idx & 63;
        CP_ASYNC16(sb + (uint32_t)(r * PA + c4 * 4) * 4u,
                   x + (size_t)(row0 + r) * E_ + c4 * 4);
    }
    if (tid < 64)
        CP_ASYNC16(sb + (uint32_t)(XF1 + tid * 4) * 4u, bias + tid * 4);

    float acc[8][4];
    #pragma unroll
    for (int nt = 0; nt < 8; ++nt)
        #pragma unroll
        for (int q = 0; q < 4; ++q) acc[nt][q] = 0.f;

    const uint32_t a_base = sb
        + (uint32_t)((mwarp * 16 + (lane & 15)) * PA + ((lane >> 4) << 2)) * 4u;
    const uint32_t b_lane =
        (uint32_t)((nwarp * 64 + (lane & 7)) * PB + (((lane >> 3) & 1) << 2)) * 4u;

    produce_chunk_c1(W, sb, mb, tid, 0);
    produce_chunk_c1(W, sb, mb, tid, 1);
    produce_chunk_c1(W, sb, mb, tid, 2);

    #pragma unroll 1
    for (int c = 0; c < NCH; ++c) {
        int cp = c + 3;
        if (cp < NCH) {
            int q2 = cp >> 2;
            if (q2 >= 1)
                MBAR_WAIT(mbe + (uint32_t)(cp & 3) * 8u, (q2 - 1) & 1);
            produce_chunk_c1(W, sb, mb, tid, cp);
        }
        MBAR_WAIT(mb + (uint32_t)(c & 3) * 8u, (c >> 2) & 1);

        const uint32_t a_c = a_base + (uint32_t)c * 64u;
        const uint32_t b_c = sb + (uint32_t)(AF1 + (c & 3) * BSTG) * 4u + b_lane;
        #pragma unroll
        for (int ks = 0; ks < 2; ++ks) {
            uint32_t afr[4];
            ldsm_x4(afr, a_c + ks * 32u);
            uint32_t bfr[8][2];
            #pragma unroll
            for (int nt = 0; nt < 8; ++nt)
                ldsm_x2(bfr[nt], b_c + (uint32_t)nt * (8u * PB * 4u) + ks * 32u);
            #pragma unroll
            for (int nt = 0; nt < 8; ++nt)
                mma_tf32(acc[nt], afr, bfr[nt]);
        }
        MBAR_ARRIVE(mbe + (uint32_t)(c & 3) * 8u);
    }

    #pragma unroll
    for (int r2 = 0; r2 < 2; ++r2) {
        int row = row0 + mwarp * 16 + grp + r2 * 8;
        #pragma unroll
        for (int nt = 0; nt < 8; ++nt) {
            int col = nwarp * 64 + nt * 8 + tig * 2;
            float2 bv = *reinterpret_cast<const float2*>(sm + XF1 + col);
            float2 o  = make_float2(acc[nt][r2 * 2 + 0] + bv.x,
                                    acc[nt][r2 * 2 + 1] + bv.y);
            *reinterpret_cast<float2*>(g_c1 + (size_t)row * E_ + col) = o;
        }
    }
}

// ======================= tiny side kernels =================================
__global__ void gemm_c2(const float* __restrict__ keys, const float* __restrict__ V)
{
    __shared__ float ks[E_];
    int j = blockIdx.x;
    int f = threadIdx.x;
    ks[f] = keys[j * E_ + f];
    __syncthreads();
    const float4* vp = reinterpret_cast<const float4*>(V) + (size_t)f * (E_ / 4);
    const float4* kp = reinterpret_cast<const float4*>(ks);
    float a = 0.f;
    #pragma unroll
    for (int e4 = 0; e4 < E_ / 4; ++e4) {
        float4 vv = vp[e4], k = kp[e4];
        a += vv.x * k.x + vv.y * k.y + vv.z * k.z + vv.w * k.w;
    }
    g_c2[j * E_ + f] = a;
}

// xk[b][j] = dot(x_b, key_j)
__global__ void __launch_bounds__(256) xk_kernel(const float* __restrict__ x,
                                                 const float* __restrict__ keys)
{
    __shared__ float4 xs[E_ / 4];
    int b = blockIdx.x, tid = threadIdx.x;
    if (tid < E_ / 4) xs[tid] = reinterpret_cast<const float4*>(x + (size_t)b * E_)[tid];
    __syncthreads();

    int warp = tid >> 5, lane = tid & 31;
    #pragma unroll
    for (int t = 0; t < 4; ++t) {
        int jj = warp + t * 8;
        const float4* kp = reinterpret_cast<const float4*>(keys + (size_t)jj * E_);
        float p = 0.f;
        #pragma unroll
        for (int q = 0; q < 2; ++q) {
            float4 k = kp[lane + 32 * q];
            float4 xv = xs[lane + 32 * q];
            p += xv.x * k.x + xv.y * k.y + xv.z * k.z + xv.w * k.w;
        }
        #pragma unroll
        for (int o = 16; o; o >>= 1) p += __shfl_xor_sync(0xffffffffu, p, o);
        if (lane == 0) g_xk[b * J_ + jj] = p;
    }
}

// ===========================================================================
extern "C" void kernel_launch(void* const* d_in, const int* in_sizes, int n_in,
                              void* d_out, int out_size)
{
    const float* x     = (const float*)d_in[0];
    const float* state = (const float*)d_in[1];
    const float* keys  = (const float*)d_in[2];
    const float* U     = (const float*)d_in[3];
    const float* V     = (const float*)d_in[4];
    const float* W     = (const float*)d_in[5];
    const float* bias  = (const float*)d_in[6];
    float* out = (float*)d_out;

    cudaFuncSetAttribute(c1_mma,      cudaFuncAttributeMaxDynamicSharedMemorySize, C1_SMEM);
    cudaFuncSetAttribute(memcell_mma, cudaFuncAttributeMaxDynamicSharedMemorySize, MAIN_SMEM);

    gemm_c2<<<J_, E_>>>(keys, V);
    xk_kernel<<<B_, 256>>>(x, keys);
    c1_mma<<<B_ / 32, 256, C1_SMEM>>>(x, W, bias);
    memcell_mma<<<ROWS / 128, 512, MAIN_SMEM>>>(state, U, x, out);
}

// round 11
// speedup vs baseline: 1.0566x; 1.0086x over previous
#include <cuda_runtime.h>
#include <math.h>
#include <stdint.h>

#define B_   4096
#define J_   32
#define E_   256
#define ROWS (B_ * J_)
#define NC1  (B_ / 32)               // 128 c1 CTAs (M=32 each)

// ======================= scratch (device globals) ==========================
__device__ float g_c1[B_ * E_];          // bias + x @ W^T
__device__ float g_c2[J_ * E_];          // keys @ V^T
__device__ unsigned int g_c1_done;       // c1-CTA completion counter

// ======================= PTX helpers =======================================
__device__ __forceinline__ uint32_t smem_u32(const void* p) {
    uint32_t a;
    asm("{ .reg .u64 t; cvta.to.shared.u64 t, %1; cvt.u32.u64 %0, t; }"
        : "=r"(a) : "l"(p));
    return a;
}

#define CP_ASYNC16(dst, src)                                                  \
    asm volatile("cp.async.cg.shared.global [%0], [%1], 16;"                  \
        :: "r"(dst), "l"(__cvta_generic_to_global((const void*)(src))) : "memory")

#define MBAR_INIT(addr, cnt)                                                  \
    asm volatile("mbarrier.init.shared.b64 [%0], %1;" :: "r"(addr), "r"(cnt) : "memory")

#define CP_MBAR_ARRIVE(addr)                                                  \
    asm volatile("cp.async.mbarrier.arrive.noinc.shared.b64 [%0];"            \
        :: "r"(addr) : "memory")

#define MBAR_ARRIVE(addr)                                                     \
    asm volatile("mbarrier.arrive.shared.b64 _, [%0];" :: "r"(addr) : "memory")

#define MBAR_WAIT(addr, parity) do {                                          \
    asm volatile("{\n\t.reg .pred P;\n\t"                                     \
        "WL_%=:\n\t"                                                          \
        "mbarrier.try_wait.parity.shared.b64 P, [%0], %1;\n\t"                \
        "@P bra.uni WD_%=;\n\t"                                               \
        "bra.uni WL_%=;\n\t"                                                  \
        "WD_%=:\n\t}"                                                         \
        :: "r"(addr), "r"(parity) : "memory");                                \
} while (0)

__device__ __forceinline__ void mma_tf32(float* d, const uint32_t* a,
                                         const uint32_t* b) {
    asm volatile(
        "mma.sync.aligned.m16n8k8.row.col.f32.tf32.tf32.f32 "
        "{%0,%1,%2,%3}, {%4,%5,%6,%7}, {%8,%9}, {%0,%1,%2,%3};"
        : "+f"(d[0]), "+f"(d[1]), "+f"(d[2]), "+f"(d[3])
        : "r"(a[0]), "r"(a[1]), "r"(a[2]), "r"(a[3]), "r"(b[0]), "r"(b[1]));
}

__device__ __forceinline__ void ldsm_x4(uint32_t* r, uint32_t addr) {
    asm volatile("ldmatrix.sync.aligned.m8n8.x4.shared.b16 {%0,%1,%2,%3}, [%4];"
        : "=r"(r[0]), "=r"(r[1]), "=r"(r[2]), "=r"(r[3]) : "r"(addr));
}
__device__ __forceinline__ void ldsm_x2(uint32_t* r, uint32_t addr) {
    asm volatile("ldmatrix.sync.aligned.m8n8.x2.shared.b16 {%0,%1}, [%2];"
        : "=r"(r[0]), "=r"(r[1]) : "r"(addr));
}

// ======================= smem layout =======================================
#define PA    260
#define PB    20
#define NCH   16                     // K chunks of 16
#define BSTG  5120                   // 256*20 floats per B stage
// main-CTA layout
#define AF    33280                  // 128*260 A tile; B stages follow
#define XF    (AF + 4 * BSTG)        // 53760 : x tile (4x256)
#define GF    (XF + 1024)            // 54784 : gate[128]
#define REDF  (GF + 128)             // 54912 : red[128*4]
#define INVF  (REDF + 512)           // 55424 : inv[128]
#define MBARF (INVF + 128)           // 55552 : 8 mbarriers
#define SMEMF (MBARF + 16)           // 55568 floats
#define MAIN_SMEM (SMEMF * 4)        // 222272 bytes -> 1 CTA/SM
// c1-CTA layout (within the same allocation)
#define AF1    8320                  // 32*260 A tile; B stages follow
#define XF1    (AF1 + 4 * BSTG)      // 28800 : bias
#define MB1F   (XF1 + 256)           // 29056 : 8 mbarriers

__device__ __forceinline__ void init_ring(uint32_t mb, int tid, int cnt)
{
    if (tid == 0) {
        #pragma unroll
        for (int s = 0; s < 4; ++s) {
            MBAR_INIT(mb + s * 8u, cnt);        // full
            MBAR_INIT(mb + 32u + s * 8u, cnt);  // empty
        }
    }
    __syncthreads();
}

// Issue the cp.asyncs of B chunk p (512 threads) + noinc arrive.
// B stages live at float offset `af`.
__device__ __forceinline__ void produce_chunk(const float* __restrict__ Bg,
                                              uint32_t sb, uint32_t mb,
                                              int tid, int p, uint32_t af)
{
    uint32_t bst = sb + (af + (uint32_t)(p & 3) * BSTG) * 4u;
    #pragma unroll
    for (int i = 0; i < 2; ++i) {
        int idx = tid + (i << 9);
        int f = idx >> 2, k4 = idx & 3;
        CP_ASYNC16(bst + (uint32_t)(f * PB + k4 * 4) * 4u,
                   Bg + (size_t)f * E_ + p * 16 + k4 * 4);
    }
    CP_MBAR_ARRIVE(mb + (uint32_t)(p & 3) * 8u);   // full[p&3]
}

// ======================= main-CTA body =====================================
__device__ void main_body(const float* __restrict__ state,
                          const float* __restrict__ U,
                          const float* __restrict__ x,
                          const float* __restrict__ keys,
                          float* __restrict__ out,
                          float* sm, int bid)
{
    const int tid  = threadIdx.x;
    const int lane = tid & 31;
    const int wid  = tid >> 5;
    const int grp  = lane >> 2;
    const int tig  = lane & 3;
    const int mwarp = wid >> 2;       // 0..3 (32 rows)
    const int nwarp = wid & 3;        // 0..3 (64 cols)
    const int row0 = bid * 128;
    const uint32_t sb = smem_u32(sm);
    const uint32_t mb  = sb + (uint32_t)MBARF * 4u;
    const uint32_t mbe = mb + 32u;

    init_ring(mb, tid, 512);

    // stage A (state) + x tile; tracked by chunk-0 arrive
    #pragma unroll
    for (int i = 0; i < 16; ++i) {
        int idx = tid + (i << 9);
        int r = idx >> 6, c4 = idx & 63;
        CP_ASYNC16(sb + (uint32_t)(r * PA + c4 * 4) * 4u,
                   state + (size_t)(row0 + r) * E_ + c4 * 4);
    }
    if (tid < 256)
        CP_ASYNC16(sb + (uint32_t)(XF + tid * 4) * 4u,
                   x + (size_t)(row0 >> 5) * E_ + tid * 4);

    float acc[2][8][4];
    #pragma unroll
    for (int mt = 0; mt < 2; ++mt)
        #pragma unroll
        for (int nt = 0; nt < 8; ++nt)
            #pragma unroll
            for (int q = 0; q < 4; ++q) acc[mt][nt][q] = 0.f;

    const uint32_t a_base = sb
        + (uint32_t)((mwarp * 32 + (lane & 15)) * PA + ((lane >> 4) << 2)) * 4u;
    const uint32_t b_lane =
        (uint32_t)((nwarp * 64 + (lane & 7)) * PB + (((lane >> 3) & 1) << 2)) * 4u;

    produce_chunk(U, sb, mb, tid, 0, AF);
    produce_chunk(U, sb, mb, tid, 1, AF);
    produce_chunk(U, sb, mb, tid, 2, AF);

    #pragma unroll 1
    for (int c = 0; c < NCH; ++c) {
        int cp = c + 3;
        if (cp < NCH) {
            int q2 = cp >> 2;
            if (q2 >= 1)
                MBAR_WAIT(mbe + (uint32_t)(cp & 3) * 8u, (q2 - 1) & 1);
            produce_chunk(U, sb, mb, tid, cp, AF);
        }
        MBAR_WAIT(mb + (uint32_t)(c & 3) * 8u, (c >> 2) & 1);

        const uint32_t a_c = a_base + (uint32_t)c * 64u;
        const uint32_t b_c = sb + (uint32_t)(AF + (c & 3) * BSTG) * 4u + b_lane;
        #pragma unroll
        for (int ks = 0; ks < 2; ++ks) {
            uint32_t afr[2][4];
            ldsm_x4(afr[0], a_c + ks * 32u);
            ldsm_x4(afr[1], a_c + 16u * PA * 4u + ks * 32u);
            uint32_t bfr[8][2];
            #pragma unroll
            for (int nt = 0; nt < 8; ++nt)
                ldsm_x2(bfr[nt], b_c + (uint32_t)nt * (8u * PB * 4u) + ks * 32u);
            #pragma unroll
            for (int nt = 0; nt < 8; ++nt) {
                mma_tf32(acc[0][nt], afr[0], bfr[nt]);
                mma_tf32(acc[1][nt], afr[1], bfr[nt]);
            }
        }
        MBAR_ARRIVE(mbe + (uint32_t)(c & 3) * 8u);
    }

    __syncthreads();   // all warps done with B stages

    // ---- stage keys (32 x 256, pitch PA) into the dead B-stage area ----
    #pragma unroll
    for (int i = 0; i < 4; ++i) {
        int idx = tid + (i << 9);
        int r = idx >> 6, c4 = idx & 63;
        *reinterpret_cast<float4*>(sm + AF + r * PA + c4 * 4) =
            reinterpret_cast<const float4*>(keys + (size_t)r * E_)[c4];
    }
    __syncthreads();

    // ---- fused gate: g[r] = sigmoid( x_b . (s_r + key_j) ), 4 thr/row ----
    {
        int r = tid >> 2, q = tid & 3;
        const float* arow = sm + r * PA;
        const float* krow = sm + AF + (r & 31) * PA;
        const float* xrow = sm + XF + (r >> 5) * 256;
        float dot = 0.f;
        #pragma unroll
        for (int u = 0; u < 16; ++u) {
            int f4 = u * 4 + q;
            float4 av = *reinterpret_cast<const float4*>(arow + f4 * 4);
            float4 kv = *reinterpret_cast<const float4*>(krow + f4 * 4);
            float4 xv = *reinterpret_cast<const float4*>(xrow + f4 * 4);
            dot += (av.x + kv.x) * xv.x + (av.y + kv.y) * xv.y
                 + (av.z + kv.z) * xv.z + (av.w + kv.w) * xv.w;
        }
        dot += __shfl_xor_sync(0xffffffffu, dot, 1);
        dot += __shfl_xor_sync(0xffffffffu, dot, 2);
        if (q == 0)
            sm[GF + r] = 1.f / (1.f + expf(-dot));
    }

    // ---- wait for all c1 CTAs before reading g_c1 ----
    if (tid == 0)
        while (atomicAdd(&g_c1_done, 0u) < (unsigned)NC1) {}
    __syncthreads();

    // ---- epilogue pass 1: v = s + g*relu(acc + c1 + c2) -> A smem ----
    float* red = sm + REDF;
    float* inv = sm + INVF;
    #pragma unroll
    for (int mt = 0; mt < 2; ++mt) {
        #pragma unroll
        for (int r2 = 0; r2 < 2; ++r2) {
            int rl   = mwarp * 32 + mt * 16 + grp + r2 * 8;
            int grow = row0 + rl;
            float gv = sm[GF + rl];
            const float* c1r = g_c1 + (size_t)(grow >> 5) * E_;
            const float* c2r = g_c2 + (size_t)(grow & 31) * E_;
            float ss = 0.f;
            #pragma unroll
            for (int nt = 0; nt < 8; ++nt) {
                int col = nwarp * 64 + nt * 8 + tig * 2;
                float2 sv  = *reinterpret_cast<float2*>(sm + rl * PA + col);
                float2 c1v = *reinterpret_cast<const float2*>(c1r + col);
                float2 c2v = *reinterpret_cast<const float2*>(c2r + col);
                float d0 = acc[mt][nt][r2 * 2 + 0] + c1v.x + c2v.x;
                float d1 = acc[mt][nt][r2 * 2 + 1] + c1v.y + c2v.y;
                float v0 = sv.x + gv * fmaxf(d0, 0.f);
                float v1 = sv.y + gv * fmaxf(d1, 0.f);
                ss += v0 * v0 + v1 * v1;
                *reinterpret_cast<float2*>(sm + rl * PA + col) = make_float2(v0, v1);
            }
            ss += __shfl_xor_sync(0xffffffffu, ss, 1);
            ss += __shfl_xor_sync(0xffffffffu, ss, 2);
            if (tig == 0) red[rl * 4 + nwarp] = ss;
        }
    }
    __syncthreads();
    if (tid < 128) {
        float s = red[tid * 4] + red[tid * 4 + 1]
                + red[tid * 4 + 2] + red[tid * 4 + 3];
        inv[tid] = 1.f / (sqrtf(s) + 1e-8f);
    }
    __syncthreads();

    // ---- epilogue pass 2: coalesced normalized writeback ----
    #pragma unroll
    for (int i = 0; i < 16; ++i) {
        int idx = tid + (i << 9);
        int r = idx >> 6, c4 = idx & 63;
        float iv = inv[r];
        float4 v = *reinterpret_cast<float4*>(sm + r * PA + c4 * 4);
        v.x *= iv; v.y *= iv; v.z *= iv; v.w *= iv;
        reinterpret_cast<float4*>(out + (size_t)(row0 + r) * E_)[c4] = v;
    }
}

// ======================= c1-CTA body (M=32, 512 thr) =======================
// g_c1[row][f] = bias[f] + sum_e x[row][e] * W[f][e]
__device__ void c1_body(const float* __restrict__ x,
                        const float* __restrict__ W,
                        const float* __restrict__ bias,
                        float* sm, int bid)
{
    const int tid  = threadIdx.x;
    const int lane = tid & 31;
    const int wid  = tid >> 5;
    const int grp  = lane >> 2;
    const int tig  = lane & 3;
    const int mwarp = wid >> 3;       // 0..1 (16 rows each)
    const int nwarp = wid & 7;        // 0..7 (32 cols each)
    const int row0 = bid * 32;
    const uint32_t sb = smem_u32(sm);
    const uint32_t mb  = sb + (uint32_t)MB1F * 4u;
    const uint32_t mbe = mb + 32u;

    init_ring(mb, tid, 512);

    // stage A = x rows [row0, row0+32) + bias; tracked by chunk-0 arrive
    #pragma unroll
    for (int i = 0; i < 4; ++i) {
        int idx = tid + (i << 9);
        int r = idx >> 6, c4 = idx & 63;
        CP_ASYNC16(sb + (uint32_t)(r * PA + c4 * 4) * 4u,
                   x + (size_t)(row0 + r) * E_ + c4 * 4);
    }
    if (tid < 64)
        CP_ASYNC16(sb + (uint32_t)(XF1 + tid * 4) * 4u, bias + tid * 4);

    float acc[4][4];
    #pragma unroll
    for (int nt = 0; nt < 4; ++nt)
        #pragma unroll
        for (int q = 0; q < 4; ++q) acc[nt][q] = 0.f;

    const uint32_t a_base = sb
        + (uint32_t)((mwarp * 16 + (lane & 15)) * PA + ((lane >> 4) << 2)) * 4u;
    const uint32_t b_lane =
        (uint32_t)((nwarp * 32 + (lane & 7)) * PB + (((lane >> 3) & 1) << 2)) * 4u;

    produce_chunk(W, sb, mb, tid, 0, AF1);
    produce_chunk(W, sb, mb, tid, 1, AF1);
    produce_chunk(W, sb, mb, tid, 2, AF1);

    #pragma unroll 1
    for (int c = 0; c < NCH; ++c) {
        int cp = c + 3;
        if (cp < NCH) {
            int q2 = cp >> 2;
            if (q2 >= 1)
                MBAR_WAIT(mbe + (uint32_t)(cp & 3) * 8u, (q2 - 1) & 1);
            produce_chunk(W, sb, mb, tid, cp, AF1);
        }
        MBAR_WAIT(mb + (uint32_t)(c & 3) * 8u, (c >> 2) & 1);

        const uint32_t a_c = a_base + (uint32_t)c * 64u;
        const uint32_t b_c = sb + (uint32_t)(AF1 + (c & 3) * BSTG) * 4u + b_lane;
        #pragma unroll
        for (int ks = 0; ks < 2; ++ks) {
            uint32_t afr[4];
            ldsm_x4(afr, a_c + ks * 32u);
            uint32_t bfr[4][2];
            #pragma unroll
            for (int nt = 0; nt < 4; ++nt)
                ldsm_x2(bfr[nt], b_c + (uint32_t)nt * (8u * PB * 4u) + ks * 32u);
            #pragma unroll
            for (int nt = 0; nt < 4; ++nt)
                mma_tf32(acc[nt], afr, bfr[nt]);
        }
        MBAR_ARRIVE(mbe + (uint32_t)(c & 3) * 8u);
    }

    #pragma unroll
    for (int r2 = 0; r2 < 2; ++r2) {
        int row = row0 + mwarp * 16 + grp + r2 * 8;
        #pragma unroll
        for (int nt = 0; nt < 4; ++nt) {
            int col = nwarp * 32 + nt * 8 + tig * 2;
            float2 bv = *reinterpret_cast<const float2*>(sm + XF1 + col);
            float2 o  = make_float2(acc[nt][r2 * 2 + 0] + bv.x,
                                    acc[nt][r2 * 2 + 1] + bv.y);
            *reinterpret_cast<float2*>(g_c1 + (size_t)row * E_ + col) = o;
        }
    }

    __threadfence();
    __syncthreads();
    if (tid == 0) atomicAdd(&g_c1_done, 1u);
}

// ======================= fused kernel ======================================
__global__ void __launch_bounds__(512, 1)
memcell_fused(const float* __restrict__ state, const float* __restrict__ U,
              const float* __restrict__ x, const float* __restrict__ keys,
              const float* __restrict__ W, const float* __restrict__ bias,
              float* __restrict__ out)
{
    extern __shared__ float sm[];
    if (blockIdx.x < NC1)
        c1_body(x, W, bias, sm, blockIdx.x);
    else
        main_body(state, U, x, keys, out, sm, blockIdx.x - NC1);
}

// ======================= c2 kernel (+ counter reset) =======================
__global__ void gemm_c2(const float* __restrict__ keys, const float* __restrict__ V)
{
    if (blockIdx.x == 0 && threadIdx.x == 0) g_c1_done = 0u;
    __shared__ float ks[E_];
    int j = blockIdx.x;
    int f = threadIdx.x;
    ks[f] = keys[j * E_ + f];
    __syncthreads();
    const float4* vp = reinterpret_cast<const float4*>(V) + (size_t)f * (E_ / 4);
    const float4* kp = reinterpret_cast<const float4*>(ks);
    float a = 0.f;
    #pragma unroll
    for (int e4 = 0; e4 < E_ / 4; ++e4) {
        float4 vv = vp[e4], k = kp[e4];
        a += vv.x * k.x + vv.y * k.y + vv.z * k.z + vv.w * k.w;
    }
    g_c2[j * E_ + f] = a;
}

// ===========================================================================
extern "C" void kernel_launch(void* const* d_in, const int* in_sizes, int n_in,
                              void* d_out, int out_size)
{
    const float* x     = (const float*)d_in[0];
    const float* state = (const float*)d_in[1];
    const float* keys  = (const float*)d_in[2];
    const float* U     = (const float*)d_in[3];
    const float* V     = (const float*)d_in[4];
    const float* W     = (const float*)d_in[5];
    const float* bias  = (const float*)d_in[6];
    float* out = (float*)d_out;

    cudaFuncSetAttribute(memcell_fused,
                         cudaFuncAttributeMaxDynamicSharedMemorySize, MAIN_SMEM);

    gemm_c2<<<J_, E_>>>(keys, V);
    memcell_fused<<<NC1 + ROWS / 128, 512, MAIN_SMEM>>>(state, U, x, keys,
                                                        W, bias, out);
}

// round 12
// speedup vs baseline: 1.1482x; 1.0867x over previous
#include <cuda_runtime.h>
#include <math.h>
#include <stdint.h>

#define B_   4096
#define J_   32
#define E_   256
#define ROWS (B_ * J_)
#define NC1   (B_ / 32)              // 128 c1 CTAs (M=32 each)
#define NPREP (NC1 + 1)              // + 1 c2 CTA
#define NMAIN (ROWS / 128)           // 1024 main CTAs

// ======================= scratch (device globals) ==========================
__device__ float g_c1[B_ * E_];          // bias + x @ W^T
__device__ float g_c2[J_ * E_];          // keys @ V^T
__device__ float g_zero[E_];             // zero-init "bias" for the c2 CTA
__device__ unsigned int g_prep_done;     // prep-CTA completion counter
__device__ unsigned int g_main_done;     // main-CTA completion counter

// ======================= PTX helpers =======================================
__device__ __forceinline__ uint32_t smem_u32(const void* p) {
    uint32_t a;
    asm("{ .reg .u64 t; cvta.to.shared.u64 t, %1; cvt.u32.u64 %0, t; }"
        : "=r"(a) : "l"(p));
    return a;
}

#define CP_ASYNC16(dst, src)                                                  \
    asm volatile("cp.async.cg.shared.global [%0], [%1], 16;"                  \
        :: "r"(dst), "l"(__cvta_generic_to_global((const void*)(src))) : "memory")

#define MBAR_INIT(addr, cnt)                                                  \
    asm volatile("mbarrier.init.shared.b64 [%0], %1;" :: "r"(addr), "r"(cnt) : "memory")

#define CP_MBAR_ARRIVE(addr)                                                  \
    asm volatile("cp.async.mbarrier.arrive.noinc.shared.b64 [%0];"            \
        :: "r"(addr) : "memory")

#define MBAR_ARRIVE(addr)                                                     \
    asm volatile("mbarrier.arrive.shared.b64 _, [%0];" :: "r"(addr) : "memory")

#define MBAR_WAIT(addr, parity) do {                                          \
    asm volatile("{\n\t.reg .pred P;\n\t"                                     \
        "WL_%=:\n\t"                                                          \
        "mbarrier.try_wait.parity.shared.b64 P, [%0], %1;\n\t"                \
        "@P bra.uni WD_%=;\n\t"                                               \
        "bra.uni WL_%=;\n\t"                                                  \
        "WD_%=:\n\t}"                                                         \
        :: "r"(addr), "r"(parity) : "memory");                                \
} while (0)

__device__ __forceinline__ void mma_tf32(float* d, const uint32_t* a,
                                         const uint32_t* b) {
    asm volatile(
        "mma.sync.aligned.m16n8k8.row.col.f32.tf32.tf32.f32 "
        "{%0,%1,%2,%3}, {%4,%5,%6,%7}, {%8,%9}, {%0,%1,%2,%3};"
        : "+f"(d[0]), "+f"(d[1]), "+f"(d[2]), "+f"(d[3])
        : "r"(a[0]), "r"(a[1]), "r"(a[2]), "r"(a[3]), "r"(b[0]), "r"(b[1]));
}

__device__ __forceinline__ void ldsm_x4(uint32_t* r, uint32_t addr) {
    asm volatile("ldmatrix.sync.aligned.m8n8.x4.shared.b16 {%0,%1,%2,%3}, [%4];"
        : "=r"(r[0]), "=r"(r[1]), "=r"(r[2]), "=r"(r[3]) : "r"(addr));
}
__device__ __forceinline__ void ldsm_x2(uint32_t* r, uint32_t addr) {
    asm volatile("ldmatrix.sync.aligned.m8n8.x2.shared.b16 {%0,%1}, [%2];"
        : "=r"(r[0]), "=r"(r[1]) : "r"(addr));
}

// ======================= smem layout =======================================
#define PA    260
#define PB    20
#define NCH   16                     // K chunks of 16
#define BSTG  5120                   // 256*20 floats per B stage
// main-CTA layout
#define AF    33280                  // 128*260 A tile; B stages follow
#define XF    (AF + 4 * BSTG)        // 53760 : x tile (4x256)
#define GF    (XF + 1024)            // 54784 : gate[128]
#define REDF  (GF + 128)             // 54912 : red[128*4]
#define INVF  (REDF + 512)           // 55424 : inv[128]
#define MBARF (INVF + 128)           // 55552 : 8 mbarriers
#define SMEMF (MBARF + 16)           // 55568 floats
#define MAIN_SMEM (SMEMF * 4)        // 222272 bytes -> 1 CTA/SM
// prep-CTA layout (within the same allocation)
#define AF1    8320                  // 32*260 A tile; B stages follow
#define XF1    (AF1 + 4 * BSTG)      // 28800 : bias
#define MB1F   (XF1 + 256)           // 29056 : 8 mbarriers

__device__ __forceinline__ void init_ring(uint32_t mb, int tid, int cnt)
{
    if (tid == 0) {
        #pragma unroll
        for (int s = 0; s < 4; ++s) {
            MBAR_INIT(mb + s * 8u, cnt);        // full
            MBAR_INIT(mb + 32u + s * 8u, cnt);  // empty
        }
    }
    __syncthreads();
}

// Issue the cp.asyncs of B chunk p (512 threads) + noinc arrive.
__device__ __forceinline__ void produce_chunk(const float* __restrict__ Bg,
                                              uint32_t sb, uint32_t mb,
                                              int tid, int p, uint32_t af)
{
    uint32_t bst = sb + (af + (uint32_t)(p & 3) * BSTG) * 4u;
    #pragma unroll
    for (int i = 0; i < 2; ++i) {
        int idx = tid + (i << 9);
        int f = idx >> 2, k4 = idx & 3;
        CP_ASYNC16(bst + (uint32_t)(f * PB + k4 * 4) * 4u,
                   Bg + (size_t)f * E_ + p * 16 + k4 * 4);
    }
    CP_MBAR_ARRIVE(mb + (uint32_t)(p & 3) * 8u);   // full[p&3]
}

// ======================= main-CTA body =====================================
__device__ void main_body(const float* __restrict__ state,
                          const float* __restrict__ U,
                          const float* __restrict__ x,
                          const float* __restrict__ keys,
                          float* __restrict__ out,
                          float* sm, int bid)
{
    const int tid  = threadIdx.x;
    const int lane = tid & 31;
    const int wid  = tid >> 5;
    const int grp  = lane >> 2;
    const int tig  = lane & 3;
    const int mwarp = wid >> 2;       // 0..3 (32 rows)
    const int nwarp = wid & 3;        // 0..3 (64 cols)
    const int row0 = bid * 128;
    const uint32_t sb = smem_u32(sm);
    const uint32_t mb  = sb + (uint32_t)MBARF * 4u;
    const uint32_t mbe = mb + 32u;

    init_ring(mb, tid, 512);

    // stage A (state) + x tile; tracked by chunk-0 arrive
    #pragma unroll
    for (int i = 0; i < 16; ++i) {
        int idx = tid + (i << 9);
        int r = idx >> 6, c4 = idx & 63;
        CP_ASYNC16(sb + (uint32_t)(r * PA + c4 * 4) * 4u,
                   state + (size_t)(row0 + r) * E_ + c4 * 4);
    }
    if (tid < 256)
        CP_ASYNC16(sb + (uint32_t)(XF + tid * 4) * 4u,
                   x + (size_t)(row0 >> 5) * E_ + tid * 4);

    float acc[2][8][4];
    #pragma unroll
    for (int mt = 0; mt < 2; ++mt)
        #pragma unroll
        for (int nt = 0; nt < 8; ++nt)
            #pragma unroll
            for (int q = 0; q < 4; ++q) acc[mt][nt][q] = 0.f;

    const uint32_t a_base = sb
        + (uint32_t)((mwarp * 32 + (lane & 15)) * PA + ((lane >> 4) << 2)) * 4u;
    const uint32_t b_lane =
        (uint32_t)((nwarp * 64 + (lane & 7)) * PB + (((lane >> 3) & 1) << 2)) * 4u;

    produce_chunk(U, sb, mb, tid, 0, AF);
    produce_chunk(U, sb, mb, tid, 1, AF);
    produce_chunk(U, sb, mb, tid, 2, AF);

    #pragma unroll 1
    for (int c = 0; c < NCH; ++c) {
        int cp = c + 3;
        if (cp < NCH) {
            int q2 = cp >> 2;
            if (q2 >= 1)
                MBAR_WAIT(mbe + (uint32_t)(cp & 3) * 8u, (q2 - 1) & 1);
            produce_chunk(U, sb, mb, tid, cp, AF);
        }
        MBAR_WAIT(mb + (uint32_t)(c & 3) * 8u, (c >> 2) & 1);

        const uint32_t a_c = a_base + (uint32_t)c * 64u;
        const uint32_t b_c = sb + (uint32_t)(AF + (c & 3) * BSTG) * 4u + b_lane;
        #pragma unroll
        for (int ks = 0; ks < 2; ++ks) {
            uint32_t afr[2][4];
            ldsm_x4(afr[0], a_c + ks * 32u);
            ldsm_x4(afr[1], a_c + 16u * PA * 4u + ks * 32u);
            uint32_t bfr[8][2];
            #pragma unroll
            for (int nt = 0; nt < 8; ++nt)
                ldsm_x2(bfr[nt], b_c + (uint32_t)nt * (8u * PB * 4u) + ks * 32u);
            #pragma unroll
            for (int nt = 0; nt < 8; ++nt) {
                mma_tf32(acc[0][nt], afr[0], bfr[nt]);
                mma_tf32(acc[1][nt], afr[1], bfr[nt]);
            }
        }
        MBAR_ARRIVE(mbe + (uint32_t)(c & 3) * 8u);
    }

    __syncthreads();   // all warps done with B stages

    // ---- stage keys (32 x 256, pitch PA) into the dead B-stage area ----
    #pragma unroll
    for (int i = 0; i < 4; ++i) {
        int idx = tid + (i << 9);
        int r = idx >> 6, c4 = idx & 63;
        *reinterpret_cast<float4*>(sm + AF + r * PA + c4 * 4) =
            reinterpret_cast<const float4*>(keys + (size_t)r * E_)[c4];
    }
    __syncthreads();

    // ---- fused gate: g[r] = sigmoid( x_b . (s_r + key_j) ), 4 thr/row ----
    {
        int r = tid >> 2, q = tid & 3;
        const float* arow = sm + r * PA;
        const float* krow = sm + AF + (r & 31) * PA;
        const float* xrow = sm + XF + (r >> 5) * 256;
        float dot = 0.f;
        #pragma unroll
        for (int u = 0; u < 16; ++u) {
            int f4 = u * 4 + q;
            float4 av = *reinterpret_cast<const float4*>(arow + f4 * 4);
            float4 kv = *reinterpret_cast<const float4*>(krow + f4 * 4);
            float4 xv = *reinterpret_cast<const float4*>(xrow + f4 * 4);
            dot += (av.x + kv.x) * xv.x + (av.y + kv.y) * xv.y
                 + (av.z + kv.z) * xv.z + (av.w + kv.w) * xv.w;
        }
        dot += __shfl_xor_sync(0xffffffffu, dot, 1);
        dot += __shfl_xor_sync(0xffffffffu, dot, 2);
        if (q == 0)
            sm[GF + r] = 1.f / (1.f + expf(-dot));
    }

    // ---- wait for all prep CTAs before reading g_c1 / g_c2 ----
    if (tid == 0)
        while (atomicAdd(&g_prep_done, 0u) < (unsigned)NPREP) {}
    __syncthreads();

    // ---- epilogue pass 1: v = s + g*relu(acc + c1 + c2) -> A smem ----
    float* red = sm + REDF;
    float* inv = sm + INVF;
    #pragma unroll
    for (int mt = 0; mt < 2; ++mt) {
        #pragma unroll
        for (int r2 = 0; r2 < 2; ++r2) {
            int rl   = mwarp * 32 + mt * 16 + grp + r2 * 8;
            int grow = row0 + rl;
            float gv = sm[GF + rl];
            const float* c1r = g_c1 + (size_t)(grow >> 5) * E_;
            const float* c2r = g_c2 + (size_t)(grow & 31) * E_;
            float ss = 0.f;
            #pragma unroll
            for (int nt = 0; nt < 8; ++nt) {
                int col = nwarp * 64 + nt * 8 + tig * 2;
                float2 sv  = *reinterpret_cast<float2*>(sm + rl * PA + col);
                float2 c1v = *reinterpret_cast<const float2*>(c1r + col);
                float2 c2v = *reinterpret_cast<const float2*>(c2r + col);
                float d0 = acc[mt][nt][r2 * 2 + 0] + c1v.x + c2v.x;
                float d1 = acc[mt][nt][r2 * 2 + 1] + c1v.y + c2v.y;
                float v0 = sv.x + gv * fmaxf(d0, 0.f);
                float v1 = sv.y + gv * fmaxf(d1, 0.f);
                ss += v0 * v0 + v1 * v1;
                *reinterpret_cast<float2*>(sm + rl * PA + col) = make_float2(v0, v1);
            }
            ss += __shfl_xor_sync(0xffffffffu, ss, 1);
            ss += __shfl_xor_sync(0xffffffffu, ss, 2);
            if (tig == 0) red[rl * 4 + nwarp] = ss;
        }
    }
    __syncthreads();
    if (tid < 128) {
        float s = red[tid * 4] + red[tid * 4 + 1]
                + red[tid * 4 + 2] + red[tid * 4 + 3];
        inv[tid] = 1.f / (sqrtf(s) + 1e-8f);
    }
    __syncthreads();

    // ---- epilogue pass 2: coalesced normalized writeback ----
    #pragma unroll
    for (int i = 0; i < 16; ++i) {
        int idx = tid + (i << 9);
        int r = idx >> 6, c4 = idx & 63;
        float iv = inv[r];
        float4 v = *reinterpret_cast<float4*>(sm + r * PA + c4 * 4);
        v.x *= iv; v.y *= iv; v.z *= iv; v.w *= iv;
        reinterpret_cast<float4*>(out + (size_t)(row0 + r) * E_)[c4] = v;
    }

    // ---- completion: last main CTA resets the handshake counters ----
    __syncthreads();
    if (tid == 0) {
        unsigned v = atomicAdd(&g_main_done, 1u);
        if (v == (unsigned)(NMAIN - 1)) {
            atomicExch(&g_prep_done, 0u);
            atomicExch(&g_main_done, 0u);
        }
    }
}

// ======================= prep-CTA body (M=32 GEMM, 512 thr) ================
// outp[row0+r][f] = bias[f] + sum_e A[row0+r][e] * Bmat[f][e]
__device__ void prep_body(const float* __restrict__ A,
                          const float* __restrict__ Bmat,
                          const float* __restrict__ bias,
                          float* __restrict__ outp, int row0,
                          float* sm)
{
    const int tid  = threadIdx.x;
    const int lane = tid & 31;
    const int wid  = tid >> 5;
    const int grp  = lane >> 2;
    const int tig  = lane & 3;
    const int mwarp = wid >> 3;       // 0..1 (16 rows each)
    const int nwarp = wid & 7;        // 0..7 (32 cols each)
    const uint32_t sb = smem_u32(sm);
    const uint32_t mb  = sb + (uint32_t)MB1F * 4u;
    const uint32_t mbe = mb + 32u;

    init_ring(mb, tid, 512);

    // stage A rows [row0, row0+32) + bias; tracked by chunk-0 arrive
    #pragma unroll
    for (int i = 0; i < 4; ++i) {
        int idx = tid + (i << 9);
        int r = idx >> 6, c4 = idx & 63;
        CP_ASYNC16(sb + (uint32_t)(r * PA + c4 * 4) * 4u,
                   A + (size_t)(row0 + r) * E_ + c4 * 4);
    }
    if (tid < 64)
        CP_ASYNC16(sb + (uint32_t)(XF1 + tid * 4) * 4u, bias + tid * 4);

    float acc[4][4];
    #pragma unroll
    for (int nt = 0; nt < 4; ++nt)
        #pragma unroll
        for (int q = 0; q < 4; ++q) acc[nt][q] = 0.f;

    const uint32_t a_base = sb
        + (uint32_t)((mwarp * 16 + (lane & 15)) * PA + ((lane >> 4) << 2)) * 4u;
    const uint32_t b_lane =
        (uint32_t)((nwarp * 32 + (lane & 7)) * PB + (((lane >> 3) & 1) << 2)) * 4u;

    produce_chunk(Bmat, sb, mb, tid, 0, AF1);
    produce_chunk(Bmat, sb, mb, tid, 1, AF1);
    produce_chunk(Bmat, sb, mb, tid, 2, AF1);

    #pragma unroll 1
    for (int c = 0; c < NCH; ++c) {
        int cp = c + 3;
        if (cp < NCH) {
            int q2 = cp >> 2;
            if (q2 >= 1)
                MBAR_WAIT(mbe + (uint32_t)(cp & 3) * 8u, (q2 - 1) & 1);
            produce_chunk(Bmat, sb, mb, tid, cp, AF1);
        }
        MBAR_WAIT(mb + (uint32_t)(c & 3) * 8u, (c >> 2) & 1);

        const uint32_t a_c = a_base + (uint32_t)c * 64u;
        const uint32_t b_c = sb + (uint32_t)(AF1 + (c & 3) * BSTG) * 4u + b_lane;
        #pragma unroll
        for (int ks = 0; ks < 2; ++ks) {
            uint32_t afr[4];
            ldsm_x4(afr, a_c + ks * 32u);
            uint32_t bfr[4][2];
            #pragma unroll
            for (int nt = 0; nt < 4; ++nt)
                ldsm_x2(bfr[nt], b_c + (uint32_t)nt * (8u * PB * 4u) + ks * 32u);
            #pragma unroll
            for (int nt = 0; nt < 4; ++nt)
                mma_tf32(acc[nt], afr, bfr[nt]);
        }
        MBAR_ARRIVE(mbe + (uint32_t)(c & 3) * 8u);
    }

    #pragma unroll
    for (int r2 = 0; r2 < 2; ++r2) {
        int row = row0 + mwarp * 16 + grp + r2 * 8;
        #pragma unroll
        for (int nt = 0; nt < 4; ++nt) {
            int col = nwarp * 32 + nt * 8 + tig * 2;
            float2 bv = *reinterpret_cast<const float2*>(sm + XF1 + col);
            float2 o  = make_float2(acc[nt][r2 * 2 + 0] + bv.x,
                                    acc[nt][r2 * 2 + 1] + bv.y);
            *reinterpret_cast<float2*>(outp + (size_t)row * E_ + col) = o;
        }
    }

    __threadfence();
    __syncthreads();
    if (tid == 0) atomicAdd(&g_prep_done, 1u);
}

// ======================= fused kernel ======================================
__global__ void __launch_bounds__(512, 1)
memcell_fused(const float* __restrict__ state, const float* __restrict__ U,
              const float* __restrict__ x, const float* __restrict__ keys,
              const float* __restrict__ V, const float* __restrict__ W,
              const float* __restrict__ bias, float* __restrict__ out)
{
    extern __shared__ float sm[];
    if (blockIdx.x < NC1)
        prep_body(x, W, bias, g_c1, blockIdx.x * 32, sm);
    else if (blockIdx.x == NC1)
        prep_body(keys, V, g_zero, g_c2, 0, sm);
    else
        main_body(state, U, x, keys, out, sm, blockIdx.x - NPREP);
}

// ===========================================================================
extern "C" void kernel_launch(void* const* d_in, const int* in_sizes, int n_in,
                              void* d_out, int out_size)
{
    const float* x     = (const float*)d_in[0];
    const float* state = (const float*)d_in[1];
    const float* keys  = (const float*)d_in[2];
    const float* U     = (const float*)d_in[3];
    const float* V     = (const float*)d_in[4];
    const float* W     = (const float*)d_in[5];
    const float* bias  = (const float*)d_in[6];
    float* out = (float*)d_out;

    cudaFuncSetAttribute(memcell_fused,
                         cudaFuncAttributeMaxDynamicSharedMemorySize, MAIN_SMEM);

    memcell_fused<<<NPREP + NMAIN, 512, MAIN_SMEM>>>(state, U, x, keys,
                                                     V, W, bias, out);
}